// round 5
// baseline (speedup 1.0000x reference)
#include <cuda_runtime.h>
#include <cuda_fp16.h>
#include <cstdint>

// Problem constants
#define M_DIM 4096
#define K_DIM 4096
#define N_DIM 11008

// GEMM tiling (int8 IMMA m16n8k32, two passes hi/lo)
#define BM 128
#define BN 128
#define BK 64                 // 64 int8 = 64B rows (4 x 16B chunks)
#define NTHREADS 256          // 8 warps: 4 along M x 2 along N; warp tile 32x64
#define NSTAGE 3

#define A_STAGE_BYTES (BM * 64)                            // 8192 (one of hi/lo)
#define B_STAGE_BYTES (BN * 64)                            // 8192
#define STAGE_BYTES   (2 * A_STAGE_BYTES + B_STAGE_BYTES)  // 24576
#define SMEM_TOTAL    (NSTAGE * STAGE_BYTES)               // 73728

// Scratch (device globals; no cudaMalloc allowed)
__device__ int8_t g_Xhi[(size_t)M_DIM * K_DIM];   // 16 MB
__device__ int8_t g_Xlo[(size_t)M_DIM * K_DIM];   // 16 MB
__device__ int8_t g_Wq[(size_t)N_DIM * K_DIM];    // 45 MB (exact int4 values)
__device__ float  g_c[M_DIM];                     // zp correction per row
__device__ float  g_dx[M_DIM];                    // per-row quant scale

// ---------------------------------------------------------------------------
// Helpers
// ---------------------------------------------------------------------------
__device__ __forceinline__ uint32_t smem_u32(const void* p) {
    return (uint32_t)__cvta_generic_to_shared(p);
}
__device__ __forceinline__ void cp16(uint32_t s, const void* g) {
    asm volatile("cp.async.cg.shared.global [%0], [%1], 16;\n" :: "r"(s), "l"(g));
}
__device__ __forceinline__ void cp_commit() {
    asm volatile("cp.async.commit_group;\n");
}
template <int N>
__device__ __forceinline__ void cp_wait() {
    asm volatile("cp.async.wait_group %0;\n" :: "n"(N));
}
__device__ __forceinline__ void ldsm4(uint32_t* r, uint32_t addr) {
    asm volatile("ldmatrix.sync.aligned.m8n8.x4.shared.b16 {%0,%1,%2,%3}, [%4];\n"
        : "=r"(r[0]), "=r"(r[1]), "=r"(r[2]), "=r"(r[3]) : "r"(addr));
}
// int8 mma: D(s32) = A(s8) * B(s8) + C(s32), m16n8k32
__device__ __forceinline__ void imma16832(int* d, const uint32_t* a, uint32_t b0, uint32_t b1) {
    asm volatile(
        "mma.sync.aligned.m16n8k32.row.col.s32.s8.s8.s32 "
        "{%0,%1,%2,%3},{%4,%5,%6,%7},{%8,%9},{%0,%1,%2,%3};\n"
        : "+r"(d[0]), "+r"(d[1]), "+r"(d[2]), "+r"(d[3])
        : "r"(a[0]), "r"(a[1]), "r"(a[2]), "r"(a[3]), "r"(b0), "r"(b1));
}

// ---------------------------------------------------------------------------
// Prep kernel 1: X' = x*s[g]; row max -> Delta_m; hi/lo int8 split;
//                c[m] = sum_k X'[m,k]*zp[g]
// ---------------------------------------------------------------------------
__global__ void prep_x_kernel(const float* __restrict__ x,
                              const float* __restrict__ scales,
                              const float* __restrict__ zps) {
    const int m = blockIdx.x;
    const float* xr = x + (size_t)m * K_DIM;
    const size_t ob = (size_t)m * K_DIM;

    __shared__ float red[256];
    // pass 1: row max of |x*s| and csum
    float amax = 0.f, csum = 0.f;
    for (int k = threadIdx.x; k < K_DIM; k += blockDim.x) {
        int gi = k >> 6;
        float s = __ldg(scales + gi);
        float xp = xr[k] * s;
        amax = fmaxf(amax, fabsf(xp));
        csum += xp * __ldg(zps + gi);
    }
    red[threadIdx.x] = amax;
    __syncthreads();
    for (int s = 128; s > 0; s >>= 1) {
        if (threadIdx.x < s) red[threadIdx.x] = fmaxf(red[threadIdx.x], red[threadIdx.x + s]);
        __syncthreads();
    }
    const float delta = fmaxf(red[0], 1e-20f) / 127.0f;
    const float inv_d = 1.0f / delta;
    __syncthreads();
    red[threadIdx.x] = csum;
    __syncthreads();
    for (int s = 128; s > 0; s >>= 1) {
        if (threadIdx.x < s) red[threadIdx.x] += red[threadIdx.x + s];
        __syncthreads();
    }
    if (threadIdx.x == 0) { g_c[m] = red[0]; g_dx[m] = delta; }

    // pass 2: quantize (x re-read hits L1/L2)
    for (int k = threadIdx.x; k < K_DIM; k += blockDim.x) {
        int gi = k >> 6;
        float xp = xr[k] * __ldg(scales + gi);
        float q = xp * inv_d;
        int hi = __float2int_rn(q);
        hi = max(-127, min(127, hi));
        int lo = __float2int_rn((q - (float)hi) * 128.0f);
        lo = max(-127, min(127, lo));
        g_Xhi[ob + k] = (int8_t)hi;
        g_Xlo[ob + k] = (int8_t)lo;
    }
}

// ---------------------------------------------------------------------------
// Prep kernel 2: unpack int4 nibbles (low nibble = even k) to exact int8
// ---------------------------------------------------------------------------
__global__ void prep_w_kernel(const int* __restrict__ pw) {
    size_t i = (size_t)blockIdx.x * blockDim.x + threadIdx.x;
    const size_t total = (size_t)N_DIM * (K_DIM / 2);
    if (i >= total) return;
    int v = pw[i];
    int lo = v & 15;
    int hi = (v >> 4) & 15;
    lo = (lo >= 8) ? lo - 16 : lo;
    hi = (hi >= 8) ? hi - 16 : hi;
    // two int8 outputs per packed byte: even k = lo, odd k = hi
    uint16_t p = (uint16_t)((uint8_t)(int8_t)lo | ((uint16_t)(uint8_t)(int8_t)hi << 8));
    reinterpret_cast<uint16_t*>(g_Wq)[i] = p;
}

// ---------------------------------------------------------------------------
// GEMM: out[m,n] = dx[m]*(S_hi + S_lo/128) - c[m] + bias[n]
// 128x128x64 block tile, 8 warps (4x2), warp tile 32x64, m16n8k32 s8 imma,
// 3-stage cp.async pipeline, XOR-swizzled smem, exact int32 accumulation.
// ---------------------------------------------------------------------------
__global__ void __launch_bounds__(NTHREADS, 1)
gemm_kernel(const float* __restrict__ bias, float* __restrict__ out) {
    extern __shared__ __align__(1024) char smem_raw[];
    const uint32_t sbase = smem_u32(smem_raw);

    const int tid  = threadIdx.x;
    const int lane = tid & 31;
    const int warp = tid >> 5;
    const int wm = warp & 3;   // 0..3 along M (32 rows each)
    const int wn = warp >> 2;  // 0..1 along N (64 cols each)

    const int m0 = blockIdx.x * BM;
    const int n0 = blockIdx.y * BN;

    int acch[2][8][4], accl[2][8][4];
#pragma unroll
    for (int i = 0; i < 2; i++)
#pragma unroll
        for (int j = 0; j < 8; j++)
#pragma unroll
            for (int v = 0; v < 4; v++) { acch[i][j][v] = 0; accl[i][j][v] = 0; }

    const int NK = K_DIM / BK;  // 64

    // stage loader: each array 512 x 16B chunks, 2 per thread; 6 cp16/thread
#define LOAD_STAGE(S, KT)                                                          \
    {                                                                              \
        uint32_t _ah = sbase + (S) * STAGE_BYTES;                                  \
        uint32_t _al = _ah + A_STAGE_BYTES;                                        \
        uint32_t _b  = _al + A_STAGE_BYTES;                                        \
        size_t _gk = (size_t)(KT) * BK;                                            \
        _Pragma("unroll")                                                          \
        for (int i = 0; i < 2; i++) {                                              \
            int j = tid + i * 256;                                                 \
            int row = j >> 2, c = j & 3;                                           \
            uint32_t soff = (uint32_t)(row * 64 + ((c ^ ((row >> 1) & 3)) << 4));  \
            size_t ga = (size_t)(m0 + row) * K_DIM + _gk + c * 16;                 \
            cp16(_ah + soff, g_Xhi + ga);                                          \
            cp16(_al + soff, g_Xlo + ga);                                          \
            cp16(_b + soff, g_Wq + (size_t)(n0 + row) * K_DIM + _gk + c * 16);     \
        }                                                                          \
    }

    LOAD_STAGE(0, 0);
    cp_commit();
    LOAD_STAGE(1, 1);
    cp_commit();

    const int lrow  = lane & 15;       // row within a 16-row ldmatrix tile
    const int lcsel = lane >> 4;       // 0: first 16B, 1: second 16B of a k32 step

    for (int kt = 0; kt < NK; kt++) {
        cp_wait<1>();
        __syncthreads();
        if (kt + 2 < NK) LOAD_STAGE((kt + 2) % NSTAGE, kt + 2);
        cp_commit();   // one group per iteration keeps wait counts aligned

        const uint32_t aH = sbase + (kt % NSTAGE) * STAGE_BYTES;
        const uint32_t aL = aH + A_STAGE_BYTES;
        const uint32_t bT = aL + A_STAGE_BYTES;

#pragma unroll
        for (int kk = 0; kk < 2; kk++) {      // two k32 steps per BK=64
            const int ccol = kk * 2 + lcsel;  // 16B chunk within 64B row
            uint32_t ah[2][4], al[2][4], bb[4][4];
#pragma unroll
            for (int mt = 0; mt < 2; mt++) {
                int row = wm * 32 + mt * 16 + lrow;
                uint32_t soff = (uint32_t)(row * 64 + ((ccol ^ ((row >> 1) & 3)) << 4));
                ldsm4(ah[mt], aH + soff);
                ldsm4(al[mt], aL + soff);
            }
#pragma unroll
            for (int np = 0; np < 4; np++) {
                int row = wn * 64 + np * 16 + lrow;
                uint32_t soff = (uint32_t)(row * 64 + ((ccol ^ ((row >> 1) & 3)) << 4));
                ldsm4(bb[np], bT + soff);
            }
#pragma unroll
            for (int mt = 0; mt < 2; mt++) {
#pragma unroll
                for (int nt = 0; nt < 8; nt++) {
                    uint32_t b0 = bb[nt >> 1][nt & 1];
                    uint32_t b1 = bb[nt >> 1][2 + (nt & 1)];
                    imma16832(acch[mt][nt], ah[mt], b0, b1);
                    imma16832(accl[mt][nt], al[mt], b0, b1);
                }
            }
        }
    }

    // ---- epilogue: dx[m]*(S_hi + S_lo/128) + bias[n] - c[m] ----
    const int g  = lane >> 2;
    const int tg = lane & 3;
    const float inv128 = 1.0f / 128.0f;
#pragma unroll
    for (int mt = 0; mt < 2; mt++) {
        int row0 = m0 + wm * 32 + mt * 16 + g;
        int row1 = row0 + 8;
        float d0 = g_dx[row0], d1 = g_dx[row1];
        float c0 = g_c[row0],  c1 = g_c[row1];
#pragma unroll
        for (int nt = 0; nt < 8; nt++) {
            int col = n0 + wn * 64 + nt * 8 + tg * 2;
            float2 bv = *reinterpret_cast<const float2*>(bias + col);
            float2 v0, v1;
            v0.x = d0 * ((float)acch[mt][nt][0] + (float)accl[mt][nt][0] * inv128) + bv.x - c0;
            v0.y = d0 * ((float)acch[mt][nt][1] + (float)accl[mt][nt][1] * inv128) + bv.y - c0;
            v1.x = d1 * ((float)acch[mt][nt][2] + (float)accl[mt][nt][2] * inv128) + bv.x - c1;
            v1.y = d1 * ((float)acch[mt][nt][3] + (float)accl[mt][nt][3] * inv128) + bv.y - c1;
            *reinterpret_cast<float2*>(out + (size_t)row0 * N_DIM + col) = v0;
            *reinterpret_cast<float2*>(out + (size_t)row1 * N_DIM + col) = v1;
        }
    }
#undef LOAD_STAGE
}

// ---------------------------------------------------------------------------
// Launch
// ---------------------------------------------------------------------------
extern "C" void kernel_launch(void* const* d_in, const int* in_sizes, int n_in,
                              void* d_out, int out_size) {
    const float* x    = (const float*)d_in[0];
    const int*   pw   = (const int*)d_in[1];
    const float* sc   = (const float*)d_in[2];
    const float* zp   = (const float*)d_in[3];
    const float* bias = (const float*)d_in[4];
    float* out = (float*)d_out;

    prep_x_kernel<<<M_DIM, 256>>>(x, sc, zp);

    const size_t wtotal = (size_t)N_DIM * (K_DIM / 2);
    prep_w_kernel<<<(unsigned)((wtotal + 255) / 256), 256>>>(pw);

    cudaFuncSetAttribute(gemm_kernel,
                         cudaFuncAttributeMaxDynamicSharedMemorySize, SMEM_TOTAL);
    dim3 grid(M_DIM / BM, N_DIM / BN);  // (32, 86); x=m fastest keeps B shared in L2
    gemm_kernel<<<grid, NTHREADS, SMEM_TOTAL>>>(bias, out);
}

// round 6
// speedup vs baseline: 5.0655x; 5.0655x over previous
#include <cuda_runtime.h>
#include <cuda_fp16.h>
#include <cstdint>

// Problem constants
#define M_DIM 4096
#define K_DIM 4096
#define N_DIM 11008

// GEMM tiling
#define BM 128
#define BN 128
#define BK 64                 // 64 halfs = 128B rows (8 x 16B chunks)
#define NTHREADS 256          // 8 warps: 2 along M x 4 along N; warp tile 64x32
#define NSTAGE 3

#define A_STAGE_BYTES (BM * 128)                       // 16384
#define B_STAGE_BYTES (BN * 128)                       // 16384
#define STAGE_BYTES   (A_STAGE_BYTES + B_STAGE_BYTES)  // 32768
#define SMEM_TOTAL    (NSTAGE * STAGE_BYTES)           // 98304

// Scratch (device globals; no cudaMalloc allowed)
__device__ __half g_X[(size_t)M_DIM * K_DIM];   // 32 MB  (x * scale, fp16)
__device__ __half g_W[(size_t)N_DIM * K_DIM];   // 90 MB  (exact int4 values)
__device__ float  g_c[M_DIM];

// ---------------------------------------------------------------------------
// Helpers
// ---------------------------------------------------------------------------
__device__ __forceinline__ uint32_t smem_u32(const void* p) {
    return (uint32_t)__cvta_generic_to_shared(p);
}
__device__ __forceinline__ void cp16(uint32_t s, const void* g) {
    asm volatile("cp.async.cg.shared.global [%0], [%1], 16;\n" :: "r"(s), "l"(g));
}
__device__ __forceinline__ void cp_commit() {
    asm volatile("cp.async.commit_group;\n");
}
template <int N>
__device__ __forceinline__ void cp_wait() {
    asm volatile("cp.async.wait_group %0;\n" :: "n"(N));
}
__device__ __forceinline__ void ldsm4(uint32_t* r, uint32_t addr) {
    asm volatile("ldmatrix.sync.aligned.m8n8.x4.shared.b16 {%0,%1,%2,%3}, [%4];\n"
        : "=r"(r[0]), "=r"(r[1]), "=r"(r[2]), "=r"(r[3]) : "r"(addr));
}
__device__ __forceinline__ void mma16816(float* d, const uint32_t* a, uint32_t b0, uint32_t b1) {
    asm volatile(
        "mma.sync.aligned.m16n8k16.row.col.f32.f16.f16.f32 "
        "{%0,%1,%2,%3},{%4,%5,%6,%7},{%8,%9},{%0,%1,%2,%3};\n"
        : "+f"(d[0]), "+f"(d[1]), "+f"(d[2]), "+f"(d[3])
        : "r"(a[0]), "r"(a[1]), "r"(a[2]), "r"(a[3]), "r"(b0), "r"(b1));
}

// ---------------------------------------------------------------------------
// Merged prep kernel:
//   blocks [0, M_DIM):           X' = x*s[g] (fp16), c[m] = sum X'[m,k]*zp[g]
//   blocks [M_DIM, M_DIM+WB):    unpack int4 nibbles to exact fp16 W
// ---------------------------------------------------------------------------
#define W_PACK_TOTAL ((size_t)N_DIM * (K_DIM / 2))     // 22544384 halves-pairs
#define W_BLOCKS     ((unsigned)((W_PACK_TOTAL + 255) / 256))

__global__ void prep_kernel(const float* __restrict__ x,
                            const int*   __restrict__ pw,
                            const float* __restrict__ scales,
                            const float* __restrict__ zps) {
    if (blockIdx.x < M_DIM) {
        const int m = blockIdx.x;
        const float* xr = x + (size_t)m * K_DIM;
        const size_t ob = (size_t)m * K_DIM;
        float csum = 0.f;
        for (int k = threadIdx.x; k < K_DIM; k += blockDim.x) {
            int gi = k >> 6;  // group index (G=64)
            float s = __ldg(scales + gi);
            float xp = xr[k] * s;
            g_X[ob + k] = __float2half(xp);
            csum += xp * __ldg(zps + gi);
        }
        __shared__ float red[256];
        red[threadIdx.x] = csum;
        __syncthreads();
        for (int s = 128; s > 0; s >>= 1) {
            if (threadIdx.x < s) red[threadIdx.x] += red[threadIdx.x + s];
            __syncthreads();
        }
        if (threadIdx.x == 0) g_c[m] = red[0];
    } else {
        size_t i = (size_t)(blockIdx.x - M_DIM) * blockDim.x + threadIdx.x;
        if (i >= W_PACK_TOTAL) return;
        int v = pw[i];
        int lo = v & 15;
        int hi = (v >> 4) & 15;
        lo = (lo >= 8) ? lo - 16 : lo;
        hi = (hi >= 8) ? hi - 16 : hi;
        __half2 p;
        p.x = __float2half((float)lo);   // even k
        p.y = __float2half((float)hi);   // odd k
        reinterpret_cast<__half2*>(g_W)[i] = p;
    }
}

// ---------------------------------------------------------------------------
// GEMM: out[m,n] = X'[m,:] . W[n,:] - c[m] + bias[n]
// 128x128x64 block tile, 8 warps (2x4), warp tile 64x32, m16n8k16 fp16 mma,
// 3-stage cp.async pipeline, 2 CTAs/SM, XOR-swizzled 128B-row smem.
// ---------------------------------------------------------------------------
__global__ void __launch_bounds__(NTHREADS, 2)
gemm_kernel(const float* __restrict__ bias, float* __restrict__ out) {
    extern __shared__ __align__(1024) char smem_raw[];
    const uint32_t sbase = smem_u32(smem_raw);

    const int tid  = threadIdx.x;
    const int lane = tid & 31;
    const int warp = tid >> 5;
    const int wm = warp & 1;   // 0..1 along M (64 rows each)
    const int wn = warp >> 1;  // 0..3 along N (32 cols each)

    const int m0 = blockIdx.x * BM;
    const int n0 = blockIdx.y * BN;

    float acc[4][4][4];
#pragma unroll
    for (int i = 0; i < 4; i++)
#pragma unroll
        for (int j = 0; j < 4; j++)
#pragma unroll
            for (int v = 0; v < 4; v++) acc[i][j][v] = 0.f;

    const int NK = K_DIM / BK;  // 64

    // stage loader: A 1024 chunks + B 1024 chunks of 16B; 8 cp16/thread
#define LOAD_STAGE(S, KT)                                                          \
    {                                                                              \
        uint32_t _a = sbase + (S) * STAGE_BYTES;                                   \
        uint32_t _b = _a + A_STAGE_BYTES;                                          \
        size_t _gk = (size_t)(KT) * BK;                                            \
        _Pragma("unroll")                                                          \
        for (int i = 0; i < 4; i++) {                                              \
            int j = tid + i * 256;                                                 \
            int row = j >> 3, c = j & 7;                                           \
            uint32_t soff = (uint32_t)(row * 128 + ((c ^ (row & 7)) << 4));        \
            cp16(_a + soff, g_X + (size_t)(m0 + row) * K_DIM + _gk + c * 8);       \
            cp16(_b + soff, g_W + (size_t)(n0 + row) * K_DIM + _gk + c * 8);       \
        }                                                                          \
    }

    LOAD_STAGE(0, 0);
    cp_commit();
    LOAD_STAGE(1, 1);
    cp_commit();

    const int lrow  = lane & 15;       // row within a 16-row ldmatrix tile
    const int lcsel = lane >> 4;       // 0: k[0..7], 1: k[8..15]

    for (int kt = 0; kt < NK; kt++) {
        cp_wait<1>();
        __syncthreads();
        if (kt + 2 < NK) LOAD_STAGE((kt + 2) % NSTAGE, kt + 2);
        cp_commit();   // one group per iteration keeps wait counts aligned

        const uint32_t aT = sbase + (kt % NSTAGE) * STAGE_BYTES;
        const uint32_t bT = aT + A_STAGE_BYTES;

#pragma unroll
        for (int kk = 0; kk < 4; kk++) {      // 4 x K=16 steps per BK=64
            const int ccol = kk * 2 + lcsel;  // 16B chunk within 128B row
            uint32_t ah[4][4], bb[2][4];
#pragma unroll
            for (int mt = 0; mt < 4; mt++) {
                int row = wm * 64 + mt * 16 + lrow;
                uint32_t soff = (uint32_t)(row * 128 + ((ccol ^ (row & 7)) << 4));
                ldsm4(ah[mt], aT + soff);
            }
#pragma unroll
            for (int np = 0; np < 2; np++) {
                int row = wn * 32 + np * 16 + lrow;
                uint32_t soff = (uint32_t)(row * 128 + ((ccol ^ (row & 7)) << 4));
                ldsm4(bb[np], bT + soff);
            }
#pragma unroll
            for (int mt = 0; mt < 4; mt++) {
#pragma unroll
                for (int nt = 0; nt < 4; nt++) {
                    uint32_t b0 = bb[nt >> 1][nt & 1];
                    uint32_t b1 = bb[nt >> 1][2 + (nt & 1)];
                    mma16816(acc[mt][nt], ah[mt], b0, b1);
                }
            }
        }
    }

    // ---- epilogue: + bias[n] - c[m] ----
    const int g  = lane >> 2;
    const int tg = lane & 3;
#pragma unroll
    for (int mt = 0; mt < 4; mt++) {
        int row0 = m0 + wm * 64 + mt * 16 + g;
        int row1 = row0 + 8;
        float c0 = g_c[row0];
        float c1 = g_c[row1];
#pragma unroll
        for (int nt = 0; nt < 4; nt++) {
            int col = n0 + wn * 32 + nt * 8 + tg * 2;
            float2 bv = *reinterpret_cast<const float2*>(bias + col);
            float2 v0, v1;
            v0.x = acc[mt][nt][0] + bv.x - c0;
            v0.y = acc[mt][nt][1] + bv.y - c0;
            v1.x = acc[mt][nt][2] + bv.x - c1;
            v1.y = acc[mt][nt][3] + bv.y - c1;
            *reinterpret_cast<float2*>(out + (size_t)row0 * N_DIM + col) = v0;
            *reinterpret_cast<float2*>(out + (size_t)row1 * N_DIM + col) = v1;
        }
    }
#undef LOAD_STAGE
}

// ---------------------------------------------------------------------------
// Launch
// ---------------------------------------------------------------------------
extern "C" void kernel_launch(void* const* d_in, const int* in_sizes, int n_in,
                              void* d_out, int out_size) {
    const float* x    = (const float*)d_in[0];
    const int*   pw   = (const int*)d_in[1];
    const float* sc   = (const float*)d_in[2];
    const float* zp   = (const float*)d_in[3];
    const float* bias = (const float*)d_in[4];
    float* out = (float*)d_out;

    prep_kernel<<<M_DIM + W_BLOCKS, 256>>>(x, pw, sc, zp);

    cudaFuncSetAttribute(gemm_kernel,
                         cudaFuncAttributeMaxDynamicSharedMemorySize, SMEM_TOTAL);
    dim3 grid(M_DIM / BM, N_DIM / BN);  // (32, 86); x=m fastest keeps B shared in L2
    gemm_kernel<<<grid, NTHREADS, SMEM_TOTAL>>>(bias, out);
}

// round 9
// speedup vs baseline: 5.4886x; 1.0835x over previous
#include <cuda_runtime.h>
#include <cuda_fp16.h>
#include <cstdint>

// Problem constants
#define M_DIM 4096
#define K_DIM 4096
#define N_DIM 11008

// GEMM tiling
#define BM 128
#define BN 128
#define BK 64                 // 64 halfs = 128B rows (8 x 16B chunks)
#define NTHREADS 256          // 8 warps: 2 along M x 4 along N; warp tile 64x32
#define NSTAGE 3

#define A_STAGE_BYTES (BM * 128)                       // 16384
#define B_STAGE_BYTES (BN * 128)                       // 16384
#define STAGE_BYTES   (A_STAGE_BYTES + B_STAGE_BYTES)  // 32768
#define SMEM_TOTAL    (NSTAGE * STAGE_BYTES)           // 98304

// Scratch (device globals; no cudaMalloc allowed)
__device__ __half g_X[(size_t)M_DIM * K_DIM];   // 32 MB  (x * scale, fp16)
__device__ __half g_W[(size_t)N_DIM * K_DIM];   // 90 MB  (exact int4 values)
__device__ float  g_c[M_DIM];

// ---------------------------------------------------------------------------
// Helpers
// ---------------------------------------------------------------------------
__device__ __forceinline__ uint32_t smem_u32(const void* p) {
    return (uint32_t)__cvta_generic_to_shared(p);
}
__device__ __forceinline__ void cp16(uint32_t s, const void* g) {
    asm volatile("cp.async.cg.shared.global [%0], [%1], 16;\n" :: "r"(s), "l"(g));
}
__device__ __forceinline__ void cp_commit() {
    asm volatile("cp.async.commit_group;\n");
}
template <int N>
__device__ __forceinline__ void cp_wait() {
    asm volatile("cp.async.wait_group %0;\n" :: "n"(N));
}
__device__ __forceinline__ void ldsm4(uint32_t* r, uint32_t addr) {
    asm volatile("ldmatrix.sync.aligned.m8n8.x4.shared.b16 {%0,%1,%2,%3}, [%4];\n"
        : "=r"(r[0]), "=r"(r[1]), "=r"(r[2]), "=r"(r[3]) : "r"(addr));
}
__device__ __forceinline__ void mma16816(float* d, const uint32_t* a, uint32_t b0, uint32_t b1) {
    asm volatile(
        "mma.sync.aligned.m16n8k16.row.col.f32.f16.f16.f32 "
        "{%0,%1,%2,%3},{%4,%5,%6,%7},{%8,%9},{%0,%1,%2,%3};\n"
        : "+f"(d[0]), "+f"(d[1]), "+f"(d[2]), "+f"(d[3])
        : "r"(a[0]), "r"(a[1]), "r"(a[2]), "r"(a[3]), "r"(b0), "r"(b1));
}

// ---------------------------------------------------------------------------
// Merged prep kernel:
//   blocks [0, M_DIM):   X' = x*s[g] (fp16, float4 path), c[m] reduction
//   blocks [M_DIM, ...): unpack int4 (one packed byte per int32!) to fp16 W
// ---------------------------------------------------------------------------
#define W_PACK_TOTAL ((size_t)N_DIM * (K_DIM / 2))       // int32 count (1 byte each)
#define W_VEC_TOTAL  (W_PACK_TOTAL / 4)                  // int4 groups of 4 values
#define W_BLOCKS     ((unsigned)((W_VEC_TOTAL + 255) / 256))

__global__ void prep_kernel(const float* __restrict__ x,
                            const int*   __restrict__ pw,
                            const float* __restrict__ scales,
                            const float* __restrict__ zps) {
    if (blockIdx.x < M_DIM) {
        const int m = blockIdx.x;
        const float4* xr = reinterpret_cast<const float4*>(x + (size_t)m * K_DIM);
        __half2* xo = reinterpret_cast<__half2*>(g_X + (size_t)m * K_DIM);
        float csum = 0.f;
#pragma unroll
        for (int it = 0; it < 4; it++) {
            int q = threadIdx.x + it * 256;          // float4 index; k = 4q
            int gi = q >> 4;                         // (4q)>>6; all 4 share gi
            float s = __ldg(scales + gi);
            float z = __ldg(zps + gi);
            float4 v = xr[q];
            float a0 = v.x * s, a1 = v.y * s, a2 = v.z * s, a3 = v.w * s;
            xo[q * 2 + 0] = __floats2half2_rn(a0, a1);
            xo[q * 2 + 1] = __floats2half2_rn(a2, a3);
            csum += (a0 + a1 + a2 + a3) * z;
        }
        __shared__ float red[256];
        red[threadIdx.x] = csum;
        __syncthreads();
        for (int s = 128; s > 0; s >>= 1) {
            if (threadIdx.x < s) red[threadIdx.x] += red[threadIdx.x + s];
            __syncthreads();
        }
        if (threadIdx.x == 0) g_c[m] = red[0];
    } else {
        // Each int32 of pw holds ONE packed byte (two int4 nibbles).
        // 4 int32 -> 4 half2 -> one uint4 store.
        size_t i = (size_t)(blockIdx.x - M_DIM) * blockDim.x + threadIdx.x;
        if (i >= W_VEC_TOTAL) return;
        int4 v4 = reinterpret_cast<const int4*>(pw)[i];
        const uint32_t bias2 = 0x64086408u;          // half2(1032, 1032)
        int vv[4] = {v4.x, v4.y, v4.z, v4.w};
        uint32_t h[4];
#pragma unroll
        for (int j = 0; j < 4; j++) {
            uint32_t byte = (uint32_t)vv[j] & 0xFFu;
            // lo nibble (even k) -> low half, hi nibble (odd k) -> high half
            uint32_t pair = (byte & 0xFu) | ((byte & 0xF0u) << 12);
            pair = (pair ^ 0x00080008u) | 0x64006400u;   // half(1024 + ((v+8)&15))
            __half2 r = __hsub2(*reinterpret_cast<__half2*>(&pair),
                                *reinterpret_cast<const __half2*>(&bias2));
            h[j] = *reinterpret_cast<uint32_t*>(&r);
        }
        reinterpret_cast<uint4*>(g_W)[i] = make_uint4(h[0], h[1], h[2], h[3]);
    }
}

// ---------------------------------------------------------------------------
// GEMM: out[m,n] = X'[m,:] . W[n,:] - c[m] + bias[n]
// 128x128x64 block tile, 8 warps (2x4), warp tile 64x32, m16n8k16 fp16 mma,
// 3-stage cp.async pipeline, 2 CTAs/SM, XOR-swizzled 128B-row smem,
// hoisted swizzle bases (per-kk address = base ^ (kk<<5)).
// ---------------------------------------------------------------------------
__global__ void __launch_bounds__(NTHREADS, 2)
gemm_kernel(const float* __restrict__ bias, float* __restrict__ out) {
    extern __shared__ __align__(1024) char smem_raw[];
    const uint32_t sbase = smem_u32(smem_raw);

    const int tid  = threadIdx.x;
    const int lane = tid & 31;
    const int warp = tid >> 5;
    const int wm = warp & 1;   // 0..1 along M (64 rows each)
    const int wn = warp >> 1;  // 0..3 along N (32 cols each)

    const int m0 = blockIdx.x * BM;
    const int n0 = blockIdx.y * BN;

    float acc[4][4][4];
#pragma unroll
    for (int i = 0; i < 4; i++)
#pragma unroll
        for (int j = 0; j < 4; j++)
#pragma unroll
            for (int v = 0; v < 4; v++) acc[i][j][v] = 0.f;

    const int NK = K_DIM / BK;  // 64

    // ---- hoisted ldsm swizzle bases (within-stage offsets) ----
    const int lrow  = lane & 15;
    const int lcsel = lane >> 4;
    uint32_t offA[4], offB[2];
#pragma unroll
    for (int mt = 0; mt < 4; mt++) {
        int row = wm * 64 + mt * 16 + lrow;
        offA[mt] = (uint32_t)(row * 128 + ((lcsel ^ (row & 7)) << 4));
    }
#pragma unroll
    for (int np = 0; np < 2; np++) {
        int row = wn * 32 + np * 16 + lrow;
        offB[np] = (uint32_t)(A_STAGE_BYTES + row * 128 + ((lcsel ^ (row & 7)) << 4));
    }

    // ---- hoisted loader state: per-thread pointers + one swizzled smem off ----
    const int ldrow = tid >> 3;         // 0..31 (plus i*32)
    const int ldc   = tid & 7;          // 16B chunk within 128B row
    const char* pA = (const char*)(g_X + (size_t)(m0 + ldrow) * K_DIM) + ldc * 16;
    const char* pB = (const char*)(g_W + (size_t)(n0 + ldrow) * K_DIM) + ldc * 16;
    const uint32_t sOff = (uint32_t)(ldrow * 128 + ((ldc ^ (ldrow & 7)) << 4));
    const size_t GROWSTRIDE = (size_t)32 * K_DIM * 2;  // 32 rows in bytes

    // LOAD_STAGE: 8 cp16/thread; pA/pB advance +128B after each call
#define LOAD_STAGE(S)                                                              \
    {                                                                              \
        uint32_t _s = sbase + (S) * STAGE_BYTES + sOff;                            \
        _Pragma("unroll")                                                          \
        for (int i = 0; i < 4; i++) {                                              \
            cp16(_s + i * 4096, pA + i * GROWSTRIDE);                              \
            cp16(_s + A_STAGE_BYTES + i * 4096, pB + i * GROWSTRIDE);              \
        }                                                                          \
        pA += 128; pB += 128;                                                      \
    }

    LOAD_STAGE(0);
    cp_commit();
    LOAD_STAGE(1);
    cp_commit();

    int ldst = 2;   // next stage to fill
    int cst  = 0;   // stage to compute

    for (int kt = 0; kt < NK; kt++) {
        cp_wait<1>();
        __syncthreads();
        if (kt + 2 < NK) {
            LOAD_STAGE(ldst);
            ldst = (ldst == NSTAGE - 1) ? 0 : ldst + 1;
        }
        cp_commit();   // one group per iteration keeps wait counts aligned

        const uint32_t sT = sbase + cst * STAGE_BYTES;
        cst = (cst == NSTAGE - 1) ? 0 : cst + 1;

#pragma unroll
        for (int kk = 0; kk < 4; kk++) {      // 4 x K=16 steps per BK=64
            const uint32_t kx = (uint32_t)(kk << 5);
            uint32_t ah[4][4], bb[2][4];
#pragma unroll
            for (int mt = 0; mt < 4; mt++) ldsm4(ah[mt], sT + (offA[mt] ^ kx));
#pragma unroll
            for (int np = 0; np < 2; np++) ldsm4(bb[np], sT + (offB[np] ^ kx));
#pragma unroll
            for (int mt = 0; mt < 4; mt++) {
#pragma unroll
                for (int nt = 0; nt < 4; nt++) {
                    uint32_t b0 = bb[nt >> 1][nt & 1];
                    uint32_t b1 = bb[nt >> 1][2 + (nt & 1)];
                    mma16816(acc[mt][nt], ah[mt], b0, b1);
                }
            }
        }
    }

    // ---- epilogue: + bias[n] - c[m] ----
    const int g  = lane >> 2;
    const int tg = lane & 3;
#pragma unroll
    for (int mt = 0; mt < 4; mt++) {
        int row0 = m0 + wm * 64 + mt * 16 + g;
        int row1 = row0 + 8;
        float c0 = g_c[row0];
        float c1 = g_c[row1];
#pragma unroll
        for (int nt = 0; nt < 4; nt++) {
            int col = n0 + wn * 32 + nt * 8 + tg * 2;
            float2 bv = *reinterpret_cast<const float2*>(bias + col);
            float2 v0, v1;
            v0.x = acc[mt][nt][0] + bv.x - c0;
            v0.y = acc[mt][nt][1] + bv.y - c0;
            v1.x = acc[mt][nt][2] + bv.x - c1;
            v1.y = acc[mt][nt][3] + bv.y - c1;
            *reinterpret_cast<float2*>(out + (size_t)row0 * N_DIM + col) = v0;
            *reinterpret_cast<float2*>(out + (size_t)row1 * N_DIM + col) = v1;
        }
    }
#undef LOAD_STAGE
}

// ---------------------------------------------------------------------------
// Launch
// ---------------------------------------------------------------------------
extern "C" void kernel_launch(void* const* d_in, const int* in_sizes, int n_in,
                              void* d_out, int out_size) {
    const float* x    = (const float*)d_in[0];
    const int*   pw   = (const int*)d_in[1];
    const float* sc   = (const float*)d_in[2];
    const float* zp   = (const float*)d_in[3];
    const float* bias = (const float*)d_in[4];
    float* out = (float*)d_out;

    prep_kernel<<<M_DIM + W_BLOCKS, 256>>>(x, pw, sc, zp);

    cudaFuncSetAttribute(gemm_kernel,
                         cudaFuncAttributeMaxDynamicSharedMemorySize, SMEM_TOTAL);
    dim3 grid(M_DIM / BM, N_DIM / BN);  // (32, 86); x=m fastest keeps B shared in L2
    gemm_kernel<<<grid, NTHREADS, SMEM_TOTAL>>>(bias, out);
}

// round 10
// speedup vs baseline: 5.6821x; 1.0353x over previous
#include <cuda_runtime.h>
#include <cuda_fp16.h>
#include <cstdint>

// Problem constants
#define M_DIM 4096
#define K_DIM 4096
#define N_DIM 11008

// GEMM tiling
#define BM 128
#define BN 128
#define BK 64                 // 64 halfs = 128B rows (8 x 16B chunks)
#define NTHREADS 256          // 8 warps: 2 along M x 4 along N; warp tile 64x32
#define NSTAGE 3

#define A_STAGE_BYTES (BM * 128)                       // 16384
#define B_STAGE_BYTES (BN * 128)                       // 16384
#define STAGE_BYTES   (A_STAGE_BYTES + B_STAGE_BYTES)  // 32768
#define SMEM_TOTAL    (NSTAGE * STAGE_BYTES)           // 98304

// Scratch (device globals; no cudaMalloc allowed)
__device__ __half g_X[(size_t)M_DIM * K_DIM];   // 32 MB  (x * scale, fp16)
__device__ __half g_W[(size_t)N_DIM * K_DIM];   // 90 MB  (exact int4 values)
__device__ float  g_c[M_DIM];

// ---------------------------------------------------------------------------
// Helpers
// ---------------------------------------------------------------------------
__device__ __forceinline__ uint32_t smem_u32(const void* p) {
    return (uint32_t)__cvta_generic_to_shared(p);
}
__device__ __forceinline__ void cp16(uint32_t s, const void* g) {
    asm volatile("cp.async.cg.shared.global [%0], [%1], 16;\n" :: "r"(s), "l"(g));
}
__device__ __forceinline__ void cp_commit() {
    asm volatile("cp.async.commit_group;\n");
}
template <int N>
__device__ __forceinline__ void cp_wait() {
    asm volatile("cp.async.wait_group %0;\n" :: "n"(N));
}
__device__ __forceinline__ void ldsm4(uint32_t* r, uint32_t addr) {
    asm volatile("ldmatrix.sync.aligned.m8n8.x4.shared.b16 {%0,%1,%2,%3}, [%4];\n"
        : "=r"(r[0]), "=r"(r[1]), "=r"(r[2]), "=r"(r[3]) : "r"(addr));
}
__device__ __forceinline__ void mma16816(float* d, const uint32_t* a, uint32_t b0, uint32_t b1) {
    asm volatile(
        "mma.sync.aligned.m16n8k16.row.col.f32.f16.f16.f32 "
        "{%0,%1,%2,%3},{%4,%5,%6,%7},{%8,%9},{%0,%1,%2,%3};\n"
        : "+f"(d[0]), "+f"(d[1]), "+f"(d[2]), "+f"(d[3])
        : "r"(a[0]), "r"(a[1]), "r"(a[2]), "r"(a[3]), "r"(b0), "r"(b1));
}

// ---------------------------------------------------------------------------
// Merged prep kernel:
//   blocks [0, M_DIM):   X' = x*s[g] (fp16, float4 path), c[m] reduction
//   blocks [M_DIM, ...): unpack int4 (one packed byte per int32) to fp16 W
// ---------------------------------------------------------------------------
#define W_PACK_TOTAL ((size_t)N_DIM * (K_DIM / 2))       // int32 count (1 byte each)
#define W_VEC_TOTAL  (W_PACK_TOTAL / 4)                  // int4 groups of 4 values
#define W_BLOCKS     ((unsigned)((W_VEC_TOTAL + 255) / 256))

__global__ void prep_kernel(const float* __restrict__ x,
                            const int*   __restrict__ pw,
                            const float* __restrict__ scales,
                            const float* __restrict__ zps) {
    if (blockIdx.x < M_DIM) {
        const int m = blockIdx.x;
        const float4* xr = reinterpret_cast<const float4*>(x + (size_t)m * K_DIM);
        __half2* xo = reinterpret_cast<__half2*>(g_X + (size_t)m * K_DIM);
        float csum = 0.f;
#pragma unroll
        for (int it = 0; it < 4; it++) {
            int q = threadIdx.x + it * 256;          // float4 index; k = 4q
            int gi = q >> 4;                         // (4q)>>6; all 4 share gi
            float s = __ldg(scales + gi);
            float z = __ldg(zps + gi);
            float4 v = xr[q];
            float a0 = v.x * s, a1 = v.y * s, a2 = v.z * s, a3 = v.w * s;
            xo[q * 2 + 0] = __floats2half2_rn(a0, a1);
            xo[q * 2 + 1] = __floats2half2_rn(a2, a3);
            csum += (a0 + a1 + a2 + a3) * z;
        }
        __shared__ float red[256];
        red[threadIdx.x] = csum;
        __syncthreads();
        for (int s = 128; s > 0; s >>= 1) {
            if (threadIdx.x < s) red[threadIdx.x] += red[threadIdx.x + s];
            __syncthreads();
        }
        if (threadIdx.x == 0) g_c[m] = red[0];
    } else {
        // Each int32 of pw holds ONE packed byte (two int4 nibbles).
        size_t i = (size_t)(blockIdx.x - M_DIM) * blockDim.x + threadIdx.x;
        if (i >= W_VEC_TOTAL) return;
        int4 v4 = reinterpret_cast<const int4*>(pw)[i];
        const uint32_t bias2 = 0x64086408u;          // half2(1032, 1032)
        int vv[4] = {v4.x, v4.y, v4.z, v4.w};
        uint32_t h[4];
#pragma unroll
        for (int j = 0; j < 4; j++) {
            uint32_t byte = (uint32_t)vv[j] & 0xFFu;
            // lo nibble (even k) -> low half, hi nibble (odd k) -> high half
            uint32_t pair = (byte & 0xFu) | ((byte & 0xF0u) << 12);
            pair = (pair ^ 0x00080008u) | 0x64006400u;   // half(1024 + ((v+8)&15))
            __half2 r = __hsub2(*reinterpret_cast<__half2*>(&pair),
                                *reinterpret_cast<const __half2*>(&bias2));
            h[j] = *reinterpret_cast<uint32_t*>(&r);
        }
        reinterpret_cast<uint4*>(g_W)[i] = make_uint4(h[0], h[1], h[2], h[3]);
    }
}

// ---------------------------------------------------------------------------
// GEMM: out[m,n] = X'[m,:] . W[n,:] - c[m] + bias[n]
// 128x128x64 block tile, 8 warps (2x4), warp tile 64x32, m16n8k16 fp16 mma,
// 3-stage cp.async pipeline, 2 CTAs/SM, XOR-swizzled 128B-row smem,
// hoisted swizzle bases, B-fragment double buffering, cp.async spread over kk.
// ---------------------------------------------------------------------------
__global__ void __launch_bounds__(NTHREADS, 2)
gemm_kernel(const float* __restrict__ bias, float* __restrict__ out) {
    extern __shared__ __align__(1024) char smem_raw[];
    const uint32_t sbase = smem_u32(smem_raw);

    const int tid  = threadIdx.x;
    const int lane = tid & 31;
    const int warp = tid >> 5;
    const int wm = warp & 1;   // 0..1 along M (64 rows each)
    const int wn = warp >> 1;  // 0..3 along N (32 cols each)

    const int m0 = blockIdx.x * BM;
    const int n0 = blockIdx.y * BN;

    float acc[4][4][4];
#pragma unroll
    for (int i = 0; i < 4; i++)
#pragma unroll
        for (int j = 0; j < 4; j++)
#pragma unroll
            for (int v = 0; v < 4; v++) acc[i][j][v] = 0.f;

    const int NK = K_DIM / BK;  // 64

    // ---- hoisted ldsm swizzle bases (within-stage offsets) ----
    const int lrow  = lane & 15;
    const int lcsel = lane >> 4;
    uint32_t offA[4], offB[2];
#pragma unroll
    for (int mt = 0; mt < 4; mt++) {
        int row = wm * 64 + mt * 16 + lrow;
        offA[mt] = (uint32_t)(row * 128 + ((lcsel ^ (row & 7)) << 4));
    }
#pragma unroll
    for (int np = 0; np < 2; np++) {
        int row = wn * 32 + np * 16 + lrow;
        offB[np] = (uint32_t)(A_STAGE_BYTES + row * 128 + ((lcsel ^ (row & 7)) << 4));
    }

    // ---- hoisted loader state ----
    const int ldrow = tid >> 3;         // 0..31 (plus i*32)
    const int ldc   = tid & 7;          // 16B chunk within 128B row
    const char* pA = (const char*)(g_X + (size_t)(m0 + ldrow) * K_DIM) + ldc * 16;
    const char* pB = (const char*)(g_W + (size_t)(n0 + ldrow) * K_DIM) + ldc * 16;
    const uint32_t sOff = (uint32_t)(ldrow * 128 + ((ldc ^ (ldrow & 7)) << 4));
    const size_t GROWSTRIDE = (size_t)32 * K_DIM * 2;  // 32 rows in bytes

    // full-stage loader used for the prologue only
#define LOAD_STAGE(S)                                                              \
    {                                                                              \
        uint32_t _s = sbase + (S) * STAGE_BYTES + sOff;                            \
        _Pragma("unroll")                                                          \
        for (int i = 0; i < 4; i++) {                                              \
            cp16(_s + i * 4096, pA + i * GROWSTRIDE);                              \
            cp16(_s + A_STAGE_BYTES + i * 4096, pB + i * GROWSTRIDE);              \
        }                                                                          \
        pA += 128; pB += 128;                                                      \
    }

    LOAD_STAGE(0);
    cp_commit();
    LOAD_STAGE(1);
    cp_commit();

    int ldst = 2;   // next stage to fill
    int cst  = 0;   // stage to compute

    for (int kt = 0; kt < NK; kt++) {
        cp_wait<1>();
        __syncthreads();

        const bool doLoad = (kt + 2 < NK);
        const uint32_t sT = sbase + cst * STAGE_BYTES;
        cst = (cst == NSTAGE - 1) ? 0 : cst + 1;
        const uint32_t sL = sbase + ldst * STAGE_BYTES + sOff;
        if (doLoad) ldst = (ldst == NSTAGE - 1) ? 0 : ldst + 1;

        // B fragment double buffer: preload kk=0
        uint32_t bb[2][2][4];
        ldsm4(bb[0][0], sT + offB[0]);
        ldsm4(bb[0][1], sT + offB[1]);

#pragma unroll
        for (int kk = 0; kk < 4; kk++) {      // 4 x K=16 steps per BK=64
            const uint32_t kx = (uint32_t)(kk << 5);
            const int cur = kk & 1;
            uint32_t ah[4][4];
            // A fragments for this kk (critical path: issue first)
#pragma unroll
            for (int mt = 0; mt < 4; mt++) ldsm4(ah[mt], sT + (offA[mt] ^ kx));
            // prefetch B fragments for kk+1
            if (kk < 3) {
                const uint32_t kx2 = (uint32_t)((kk + 1) << 5);
                ldsm4(bb[cur ^ 1][0], sT + (offB[0] ^ kx2));
                ldsm4(bb[cur ^ 1][1], sT + (offB[1] ^ kx2));
            }
            // spread stage-fill: 2 of 8 cp.async per kk
            if (doLoad) {
                cp16(sL + kk * 4096, pA + kk * GROWSTRIDE);
                cp16(sL + A_STAGE_BYTES + kk * 4096, pB + kk * GROWSTRIDE);
            }
#pragma unroll
            for (int mt = 0; mt < 4; mt++) {
#pragma unroll
                for (int nt = 0; nt < 4; nt++) {
                    uint32_t b0 = bb[cur][nt >> 1][nt & 1];
                    uint32_t b1 = bb[cur][nt >> 1][2 + (nt & 1)];
                    mma16816(acc[mt][nt], ah[mt], b0, b1);
                }
            }
        }
        if (doLoad) { pA += 128; pB += 128; }
        cp_commit();   // one group per iteration keeps wait counts aligned
    }

    // ---- epilogue: + bias[n] - c[m] ----
    const int g  = lane >> 2;
    const int tg = lane & 3;
#pragma unroll
    for (int mt = 0; mt < 4; mt++) {
        int row0 = m0 + wm * 64 + mt * 16 + g;
        int row1 = row0 + 8;
        float c0 = g_c[row0];
        float c1 = g_c[row1];
#pragma unroll
        for (int nt = 0; nt < 4; nt++) {
            int col = n0 + wn * 32 + nt * 8 + tg * 2;
            float2 bv = *reinterpret_cast<const float2*>(bias + col);
            float2 v0, v1;
            v0.x = acc[mt][nt][0] + bv.x - c0;
            v0.y = acc[mt][nt][1] + bv.y - c0;
            v1.x = acc[mt][nt][2] + bv.x - c1;
            v1.y = acc[mt][nt][3] + bv.y - c1;
            *reinterpret_cast<float2*>(out + (size_t)row0 * N_DIM + col) = v0;
            *reinterpret_cast<float2*>(out + (size_t)row1 * N_DIM + col) = v1;
        }
    }
#undef LOAD_STAGE
}

// ---------------------------------------------------------------------------
// Launch
// ---------------------------------------------------------------------------
extern "C" void kernel_launch(void* const* d_in, const int* in_sizes, int n_in,
                              void* d_out, int out_size) {
    const float* x    = (const float*)d_in[0];
    const int*   pw   = (const int*)d_in[1];
    const float* sc   = (const float*)d_in[2];
    const float* zp   = (const float*)d_in[3];
    const float* bias = (const float*)d_in[4];
    float* out = (float*)d_out;

    prep_kernel<<<M_DIM + W_BLOCKS, 256>>>(x, pw, sc, zp);

    cudaFuncSetAttribute(gemm_kernel,
                         cudaFuncAttributeMaxDynamicSharedMemorySize, SMEM_TOTAL);
    dim3 grid(M_DIM / BM, N_DIM / BN);  // (32, 86); x=m fastest keeps B shared in L2
    gemm_kernel<<<grid, NTHREADS, SMEM_TOTAL>>>(bias, out);
}